// round 6
// baseline (speedup 1.0000x reference)
#include <cuda_runtime.h>
#include <math.h>

#define MEL_TOT (32*512*80)
#define NB 148
#define NT 512
#define GT (NB*NT)

// ---------------- static device scratch ----------------
__device__ float g_tgtT[512*80*32];                 // [t][k][b]
__device__ float g_pre1T[(size_t)512*256*32];       // [t][c][b]
__device__ float g_pre2T[(size_t)512*256*32];       // [t][c][b]
__device__ float g_Mt[512*128];                     // [k][d]
__device__ float g_pe[(size_t)32*512*128];          // [b][t][d]
__device__ float g_part[(size_t)4*4096*32];         // [split][n][b]
__device__ float g_ahT[1024*32], g_acT[1024*32];    // [j][b]
__device__ float g_dhT[1024*32], g_dcT[1024*32];
__device__ float g_ctxT[512*32];                    // [e][b]
__device__ float g_qT[128*32];                      // [d][b]
__device__ float g_paf[(size_t)32*512*32];          // [b][t][f]
__device__ float g_aw[32*512], g_aws[32*512], g_energy[32*512];
__device__ unsigned g_arrive;                       // zero-init
__device__ unsigned g_gen;                          // zero-init

__device__ __forceinline__ float sig_(float x){
    x = fminf(fmaxf(x, -30.f), 30.f);
    return __fdividef(1.f, 1.f + __expf(-x));
}
__device__ __forceinline__ float tanh_(float x){
    float cx = fminf(fmaxf(x, -15.f), 15.f);
    float e2 = __expf(2.f*cx);
    return __fdividef(e2 - 1.f, e2 + 1.f);
}

// ---------------- prep kernels ----------------
__global__ void k_tgtT(const float* __restrict__ tgt){
    int idx = blockIdx.x*256 + threadIdx.x;
    if (idx >= 32*512*80) return;
    int b = idx / (512*80); int r = idx - b*512*80;
    int t = r / 80; int k = r - t*80;
    g_tgtT[((size_t)t*80 + k)*32 + b] = (t == 0) ? 0.f : tgt[idx - 80];
}

__global__ void k_pre1(const float* __restrict__ w1, const float* __restrict__ b1){
    int gw = blockIdx.x*8 + (threadIdx.x >> 5);
    int lane = threadIdx.x & 31;
    int t = gw >> 8, c = gw & 255;
    float acc = b1[c];
    const float4* w4 = (const float4*)(w1 + c*80);
    #pragma unroll
    for (int k = 0; k < 80; k += 4){
        float4 wv = __ldg(&w4[k >> 2]);
        const float* xp = g_tgtT + ((size_t)t*80 + k)*32 + lane;
        acc += wv.x*xp[0] + wv.y*xp[32] + wv.z*xp[64] + wv.w*xp[96];
    }
    g_pre1T[((size_t)t*256 + c)*32 + lane] = fmaxf(acc, 0.f);
}

__global__ void k_pre2(const float* __restrict__ w2, const float* __restrict__ b2){
    int gw = blockIdx.x*8 + (threadIdx.x >> 5);
    int lane = threadIdx.x & 31;
    int t = gw >> 8, c = gw & 255;
    float acc = b2[c];
    const float4* w4 = (const float4*)(w2 + c*256);
    #pragma unroll 4
    for (int k = 0; k < 256; k += 4){
        float4 wv = __ldg(&w4[k >> 2]);
        const float* xp = g_pre1T + ((size_t)t*256 + k)*32 + lane;
        acc += wv.x*xp[0] + wv.y*xp[32] + wv.z*xp[64] + wv.w*xp[96];
    }
    g_pre2T[((size_t)t*256 + c)*32 + lane] = fmaxf(acc, 0.f);
}

__global__ void k_Mt(const float* __restrict__ Mw){
    int idx = blockIdx.x*256 + threadIdx.x;
    if (idx < 128*512){ int d = idx >> 9, k = idx & 511; g_Mt[k*128 + d] = Mw[idx]; }
}

__global__ void k_pe(const float* __restrict__ enc){
    int bt = blockIdx.x;            // b*512 + t_enc
    int tid = threadIdx.x;          // 128
    __shared__ float es[512];
    const float* ep = enc + (size_t)bt*512;
    for (int i = tid; i < 512; i += 128) es[i] = ep[i];
    __syncthreads();
    float acc = 0.f;
    #pragma unroll 4
    for (int k = 0; k < 512; k += 4){
        const float* mp = g_Mt + (size_t)k*128 + tid;
        acc += es[k]*mp[0] + es[k+1]*mp[128] + es[k+2]*mp[256] + es[k+3]*mp[384];
    }
    g_pe[(size_t)bt*128 + tid] = acc;
}

// ---------------- grid barrier (all 148 blocks co-resident) ----------------
__device__ __forceinline__ void gridbar(){
    __syncthreads();
    if (threadIdx.x == 0){
        unsigned gen = *((volatile unsigned*)&g_gen);
        __threadfence();
        unsigned prev = atomicAdd(&g_arrive, 1u);
        if (prev == NB - 1){
            g_arrive = 0;
            __threadfence();
            atomicAdd(&g_gen, 1u);
        } else {
            while (*((volatile unsigned*)&g_gen) == gen) __nanosleep(64);
        }
        __threadfence();
    }
    __syncthreads();
}

// ---------------- 8-row GEMV segment: acc[i] += W[row i] . x ----------------
__device__ __forceinline__ void seg8(float acc[8], const float* __restrict__ W,
        int ldw, const float* __restrict__ xsp, int cnt, int lane){
    #pragma unroll 2
    for (int k = 0; k < cnt; k += 4){
        float x0 = xsp[(k+0)*32 + lane];
        float x1 = xsp[(k+1)*32 + lane];
        float x2 = xsp[(k+2)*32 + lane];
        float x3 = xsp[(k+3)*32 + lane];
        const float* wp = W + k;
        #pragma unroll
        for (int i = 0; i < 8; i++){
            float4 w = __ldg((const float4*)(wp + (size_t)i*ldw));
            acc[i] += x0*w.x + x1*w.y + x2*w.z + x3*w.w;
        }
    }
}

__device__ __forceinline__ void proj_warps(int nwarp, int lw, int lane, int step,
        const float* __restrict__ pw, const float* __restrict__ pb, float* __restrict__ out){
    for (int o = lw; o < 2560; o += nwarp){
        int mrow = o >> 5, b = o & 31;
        float s = 0.f;
        const float4* w4 = (const float4*)(pw + (size_t)mrow*1536);
        #pragma unroll
        for (int it = 0; it < 12; it++){
            int j = it*128 + lane*4;
            float4 w = __ldg(&w4[j >> 2]);
            const float* xp = (it < 8) ? (g_dhT + j*32 + b) : (g_ctxT + (j-1024)*32 + b);
            s += w.x*xp[0] + w.y*xp[32] + w.z*xp[64] + w.w*xp[96];
        }
        #pragma unroll
        for (int off = 16; off; off >>= 1) s += __shfl_down_sync(0xffffffffu, s, off);
        if (lane == 0) out[((size_t)b*512 + step)*80 + mrow] = s + pb[mrow];
    }
}

// ---------------- persistent decoder ----------------
__global__ void __launch_bounds__(NT, 1) k_persist(
    const float* __restrict__ enc,
    const float* __restrict__ Qw,  const float* __restrict__ Ww,
    const float* __restrict__ Lw,  const float* __restrict__ convw,
    const float* __restrict__ awih, const float* __restrict__ awhh,
    const float* __restrict__ abih, const float* __restrict__ abhh,
    const float* __restrict__ dwih, const float* __restrict__ dwhh,
    const float* __restrict__ dbih, const float* __restrict__ dbhh,
    const float* __restrict__ pw,   const float* __restrict__ pb,
    float* __restrict__ out)
{
    extern __shared__ float sh[];
    const int tid  = threadIdx.x;
    const int gtid = blockIdx.x*NT + tid;
    const int lane = tid & 31;
    const int wid  = tid >> 5;

    // phase 0: zero recurrent state
    for (int i = gtid; i < 32768; i += GT){ g_ahT[i]=0.f; g_acT[i]=0.f; g_dhT[i]=0.f; g_dcT[i]=0.f; }
    for (int i = gtid; i < 16384; i += GT){ g_ctxT[i]=0.f; g_aw[i]=0.f; g_aws[i]=0.f; }
    gridbar();

    for (int step = 0; step < 512; step++){
        // ---- P1: attn GEMM (blocks 0..127) + proj(step-1) (blocks 128..147) ----
        if (blockIdx.x < 128){
            const int KS = 448;
            int kslice = blockIdx.x >> 5;
            int k0 = kslice*KS;
            for (int idx = tid; idx < KS*32; idx += NT){
                int kk = idx >> 5, b = idx & 31, gk = k0 + kk;
                float v;
                if (gk < 256)      v = g_pre2T[((size_t)step*256 + gk)*32 + b];
                else if (gk < 768) v = g_ctxT[(gk-256)*32 + b];
                else               v = g_ahT[(gk-768)*32 + b];
                sh[idx] = v;
            }
            __syncthreads();
            int n0 = ((blockIdx.x & 31)*16 + wid)*8;
            float acc[8];
            #pragma unroll
            for (int i = 0; i < 8; i++) acc[i] = 0.f;
            int lo = k0, hi = k0 + KS;
            int c1 = min(hi, 768) - lo;
            if (c1 > 0) seg8(acc, awih + (size_t)n0*768 + lo, 768, sh, c1, lane);
            int s2 = max(lo, 768);
            if (hi > s2) seg8(acc, awhh + (size_t)n0*1024 + (s2-768), 1024,
                              sh + (s2-k0)*32, hi - s2, lane);
            #pragma unroll
            for (int i = 0; i < 8; i++)
                g_part[((size_t)kslice*4096 + n0 + i)*32 + lane] = acc[i];
        } else if (step > 0){
            int lw = (blockIdx.x - 128)*16 + wid;   // 0..319
            proj_warps(320, lw, lane, step-1, pw, pb, out);
        }
        gridbar();

        // ---- P2: attn cell ----
        if (gtid < 32768){
            int j = gtid >> 5, b = gtid & 31;
            float gi = abih[j]      + abhh[j];
            float gf = abih[1024+j] + abhh[1024+j];
            float gg = abih[2048+j] + abhh[2048+j];
            float go = abih[3072+j] + abhh[3072+j];
            #pragma unroll
            for (int s = 0; s < 4; s++){
                const float* p = g_part + (size_t)s*4096*32;
                gi += p[(size_t)j*32+b]; gf += p[(size_t)(1024+j)*32+b];
                gg += p[(size_t)(2048+j)*32+b]; go += p[(size_t)(3072+j)*32+b];
            }
            float c  = g_acT[j*32+b];
            float c2 = sig_(gf)*c + sig_(gi)*tanh_(gg);
            g_acT[j*32+b] = c2;
            g_ahT[j*32+b] = sig_(go)*tanh_(c2);
        }
        gridbar();

        // ---- P3: q = ah@Q^T (warps 0..2047) + conv features (all threads) ----
        {
            int gw = gtid >> 5;
            if (gw < 2048){
                #pragma unroll
                for (int u = 0; u < 2; u++){
                    int oo = gw*2 + u; int d = oo >> 5, b = oo & 31;
                    float s = 0.f;
                    const float4* q4 = (const float4*)(Qw + (size_t)d*1024);
                    #pragma unroll
                    for (int it = 0; it < 8; it++){
                        int j = it*128 + lane*4;
                        float4 w = __ldg(&q4[j >> 2]);
                        const float* hp = g_ahT + (size_t)j*32 + b;
                        s += w.x*hp[0] + w.y*hp[32] + w.z*hp[64] + w.w*hp[96];
                    }
                    #pragma unroll
                    for (int off = 16; off; off >>= 1) s += __shfl_down_sync(0xffffffffu, s, off);
                    if (lane == 0) g_qT[d*32 + b] = s;
                }
            }
            for (int idx = gtid; idx < 32*512*32; idx += GT){
                int b = idx >> 14; int r = idx & 16383; int t = r >> 5; int f = r & 31;
                const float* c1 = convw + f*62;
                const float* awp  = g_aw  + b*512;
                const float* awsp = g_aws + b*512;
                float s = 0.f;
                #pragma unroll
                for (int k = 0; k < 31; k++){
                    int tt = t - 15 + k;
                    if (tt >= 0 && tt < 512)
                        s += awp[tt]*__ldg(c1+k) + awsp[tt]*__ldg(c1+31+k);
                }
                g_paf[((size_t)b*512 + t)*32 + f] = s;
            }
        }
        gridbar();

        // ---- P4: energies (4 threads per (b,t)) ----
        if (gtid < 65536){
            int pairid = gtid >> 2, sub = gtid & 3;
            int b = pairid >> 9, t = pairid & 511;
            float pf[32];
            const float4* pafp = (const float4*)(g_paf + ((size_t)b*512 + t)*32);
            #pragma unroll
            for (int i = 0; i < 8; i++){
                float4 v = __ldg(&pafp[i]);
                pf[i*4] = v.x; pf[i*4+1] = v.y; pf[i*4+2] = v.z; pf[i*4+3] = v.w;
            }
            const float* pe = g_pe + ((size_t)b*512 + t)*128;
            float e = 0.f;
            #pragma unroll 1
            for (int dd = 0; dd < 32; dd++){
                int d = sub*32 + dd;
                float l = g_qT[d*32 + b] + __ldg(pe + d);
                const float4* lw4 = (const float4*)(Lw + d*32);
                #pragma unroll
                for (int i = 0; i < 8; i++){
                    float4 w = __ldg(&lw4[i]);
                    l += pf[i*4]*w.x + pf[i*4+1]*w.y + pf[i*4+2]*w.z + pf[i*4+3]*w.w;
                }
                e += __ldg(Ww + d)*tanh_(l);
            }
            e += __shfl_xor_sync(0xffffffffu, e, 1);
            e += __shfl_xor_sync(0xffffffffu, e, 2);
            if (sub == 0) g_energy[b*512 + t] = e;
        }
        gridbar();

        // ---- P5: softmax + context + aws + alignment (blocks 0..31) ----
        if (blockIdx.x < 32){
            int b = blockIdx.x;
            float* es  = sh;
            float* red = sh + 512;
            float v = g_energy[b*512 + tid];
            red[tid] = v; __syncthreads();
            for (int s = 256; s; s >>= 1){ if (tid < s) red[tid] = fmaxf(red[tid], red[tid+s]); __syncthreads(); }
            float m = red[0]; __syncthreads();
            float p = __expf(v - m);
            red[tid] = p; __syncthreads();
            for (int s = 256; s; s >>= 1){ if (tid < s) red[tid] += red[tid+s]; __syncthreads(); }
            float inv = __fdividef(1.f, red[0]);
            float a = p*inv;
            es[tid] = a;
            g_aw[b*512 + tid]   = a;
            g_aws[b*512 + tid] += a;
            out[MEL_TOT + ((size_t)b*512 + step)*512 + tid] = a;
            __syncthreads();
            float acc = 0.f;
            const float* ep = enc + (size_t)b*512*512 + tid;
            #pragma unroll 8
            for (int t = 0; t < 512; t++) acc += es[t]*ep[(size_t)t*512];
            g_ctxT[tid*32 + b] = acc;
        }
        gridbar();

        // ---- P6: dec GEMM ----
        if (blockIdx.x < 128){
            const int KS = 640;
            int kslice = blockIdx.x >> 5;
            int k0 = kslice*KS;
            for (int idx = tid; idx < KS*32; idx += NT){
                int kk = idx >> 5, b = idx & 31, gk = k0 + kk;
                float v;
                if (gk < 1024)      v = g_ahT[gk*32 + b];
                else if (gk < 1536) v = g_ctxT[(gk-1024)*32 + b];
                else                v = g_dhT[(gk-1536)*32 + b];
                sh[idx] = v;
            }
            __syncthreads();
            int n0 = ((blockIdx.x & 31)*16 + wid)*8;
            float acc[8];
            #pragma unroll
            for (int i = 0; i < 8; i++) acc[i] = 0.f;
            int lo = k0, hi = k0 + KS;
            int c1 = min(hi, 1536) - lo;
            if (c1 > 0) seg8(acc, dwih + (size_t)n0*1536 + lo, 1536, sh, c1, lane);
            int s2 = max(lo, 1536);
            if (hi > s2) seg8(acc, dwhh + (size_t)n0*1024 + (s2-1536), 1024,
                              sh + (s2-k0)*32, hi - s2, lane);
            #pragma unroll
            for (int i = 0; i < 8; i++)
                g_part[((size_t)kslice*4096 + n0 + i)*32 + lane] = acc[i];
        }
        gridbar();

        // ---- P7: dec cell ----
        if (gtid < 32768){
            int j = gtid >> 5, b = gtid & 31;
            float gi = dbih[j]      + dbhh[j];
            float gf = dbih[1024+j] + dbhh[1024+j];
            float gg = dbih[2048+j] + dbhh[2048+j];
            float go = dbih[3072+j] + dbhh[3072+j];
            #pragma unroll
            for (int s = 0; s < 4; s++){
                const float* p = g_part + (size_t)s*4096*32;
                gi += p[(size_t)j*32+b]; gf += p[(size_t)(1024+j)*32+b];
                gg += p[(size_t)(2048+j)*32+b]; go += p[(size_t)(3072+j)*32+b];
            }
            float c  = g_dcT[j*32+b];
            float c2 = sig_(gf)*c + sig_(gi)*tanh_(gg);
            g_dcT[j*32+b] = c2;
            g_dhT[j*32+b] = sig_(go)*tanh_(c2);
        }
        gridbar();
    }

    // final projection for step 511 (all warps)
    proj_warps(NB*16, gtid >> 5, lane, 511, pw, pb, out);
}

// ---------------- launch ----------------
extern "C" void kernel_launch(void* const* d_in, const int* in_sizes, int n_in,
                              void* d_out, int out_size){
    const float* enc   = (const float*)d_in[0];
    const float* tgt   = (const float*)d_in[1];
    const float* w1    = (const float*)d_in[2];
    const float* b1    = (const float*)d_in[3];
    const float* w2    = (const float*)d_in[4];
    const float* b2    = (const float*)d_in[5];
    const float* Mw    = (const float*)d_in[6];
    const float* Qw    = (const float*)d_in[7];
    const float* Ww    = (const float*)d_in[8];
    const float* Lw    = (const float*)d_in[9];
    const float* convw = (const float*)d_in[10];
    const float* awih  = (const float*)d_in[11];
    const float* awhh  = (const float*)d_in[12];
    const float* abih  = (const float*)d_in[13];
    const float* abhh  = (const float*)d_in[14];
    const float* dwih  = (const float*)d_in[15];
    const float* dwhh  = (const float*)d_in[16];
    const float* dbih  = (const float*)d_in[17];
    const float* dbhh  = (const float*)d_in[18];
    const float* pw    = (const float*)d_in[19];
    const float* pb    = (const float*)d_in[20];
    float* out = (float*)d_out;

    k_tgtT<<<(32*512*80 + 255)/256, 256>>>(tgt);
    k_pre1<<<16384, 256>>>(w1, b1);
    k_pre2<<<16384, 256>>>(w2, b2);
    k_Mt<<<256, 256>>>(Mw);
    k_pe<<<16384, 128>>>(enc);

    static int smem_set = 0;
    if (!smem_set){
        cudaFuncSetAttribute(k_persist, cudaFuncAttributeMaxDynamicSharedMemorySize, 81920);
        smem_set = 1;
    }
    k_persist<<<NB, NT, 81920>>>(enc, Qw, Ww, Lw, convw,
                                 awih, awhh, abih, abhh,
                                 dwih, dwhh, dbih, dbhh, pw, pb, out);
}

// round 7
// speedup vs baseline: 1.9045x; 1.9045x over previous
#include <cuda_runtime.h>
#include <math.h>

#define MEL_TOT (32*512*80)
#define NB 148
#define NT 512
#define GT (NB*NT)

// ---------------- static device scratch ----------------
__device__ __align__(16) float g_tgtT[512*80*32];            // [t][k][b]
__device__ __align__(16) float g_pre1T[(size_t)512*256*32];  // [t][c][b]
__device__ __align__(16) float g_pre2T[(size_t)512*256*32];  // [t][c][b]
__device__ __align__(16) float g_Mt[512*128];                // [k][d]
__device__ __align__(16) float g_pe[(size_t)32*512*128];     // [b][t][d]
__device__ __align__(16) float g_part[(size_t)4*4096*32];    // [split][n][b]
__device__ __align__(16) float g_ahT[1024*32], g_acT[1024*32]; // [j][b]
__device__ __align__(16) float g_dhT[1024*32], g_dcT[1024*32];
__device__ __align__(16) float g_ahB[32*1024], g_dhB[32*1024]; // [b][j]
__device__ __align__(16) float g_ctxT[512*32];               // [e][b]
__device__ __align__(16) float g_ctxB[32*512];               // [b][e]
__device__ __align__(16) float g_ctxP[4*512*32];             // [q][e][b]
__device__ __align__(16) float g_qB[32*128];                 // [b][d]
__device__ __align__(16) float g_paf[(size_t)32*32*512];     // [b][f][t]
__device__ __align__(16) float g_aw[32*512], g_aws[32*512], g_energy[32*512];
__device__ unsigned g_arrive;
__device__ unsigned g_gen;

__device__ __forceinline__ float sig_(float x){
    x = fminf(fmaxf(x, -30.f), 30.f);
    return __fdividef(1.f, 1.f + __expf(-x));
}
__device__ __forceinline__ float tanh_(float x){
    float cx = fminf(fmaxf(x, -15.f), 15.f);
    float e2 = __expf(2.f*cx);
    return __fdividef(e2 - 1.f, e2 + 1.f);
}

// ---------------- prep kernels ----------------
__global__ void k_tgtT(const float* __restrict__ tgt){
    int idx = blockIdx.x*256 + threadIdx.x;
    if (idx >= 32*512*80) return;
    int b = idx / (512*80); int r = idx - b*512*80;
    int t = r / 80; int k = r - t*80;
    g_tgtT[((size_t)t*80 + k)*32 + b] = (t == 0) ? 0.f : tgt[idx - 80];
}

__global__ void k_pre1(const float* __restrict__ w1, const float* __restrict__ b1){
    int gw = blockIdx.x*8 + (threadIdx.x >> 5);
    int lane = threadIdx.x & 31;
    int t = gw >> 8, c = gw & 255;
    float acc = b1[c];
    const float4* w4 = (const float4*)(w1 + c*80);
    #pragma unroll
    for (int k = 0; k < 80; k += 4){
        float4 wv = __ldg(&w4[k >> 2]);
        const float* xp = g_tgtT + ((size_t)t*80 + k)*32 + lane;
        acc += wv.x*xp[0] + wv.y*xp[32] + wv.z*xp[64] + wv.w*xp[96];
    }
    g_pre1T[((size_t)t*256 + c)*32 + lane] = fmaxf(acc, 0.f);
}

__global__ void k_pre2(const float* __restrict__ w2, const float* __restrict__ b2){
    int gw = blockIdx.x*8 + (threadIdx.x >> 5);
    int lane = threadIdx.x & 31;
    int t = gw >> 8, c = gw & 255;
    float acc = b2[c];
    const float4* w4 = (const float4*)(w2 + c*256);
    #pragma unroll 4
    for (int k = 0; k < 256; k += 4){
        float4 wv = __ldg(&w4[k >> 2]);
        const float* xp = g_pre1T + ((size_t)t*256 + k)*32 + lane;
        acc += wv.x*xp[0] + wv.y*xp[32] + wv.z*xp[64] + wv.w*xp[96];
    }
    g_pre2T[((size_t)t*256 + c)*32 + lane] = fmaxf(acc, 0.f);
}

__global__ void k_Mt(const float* __restrict__ Mw){
    int idx = blockIdx.x*256 + threadIdx.x;
    if (idx < 128*512){ int d = idx >> 9, k = idx & 511; g_Mt[k*128 + d] = Mw[idx]; }
}

__global__ void k_pe(const float* __restrict__ enc){
    int bt = blockIdx.x;            // b*512 + t_enc
    int tid = threadIdx.x;          // 128
    __shared__ float es[512];
    const float* ep = enc + (size_t)bt*512;
    for (int i = tid; i < 512; i += 128) es[i] = ep[i];
    __syncthreads();
    float acc = 0.f;
    #pragma unroll 4
    for (int k = 0; k < 512; k += 4){
        const float* mp = g_Mt + (size_t)k*128 + tid;
        acc += es[k]*mp[0] + es[k+1]*mp[128] + es[k+2]*mp[256] + es[k+3]*mp[384];
    }
    g_pe[(size_t)bt*128 + tid] = acc;
}

// ---------------- grid barrier ----------------
__device__ __forceinline__ void gridbar(){
    __syncthreads();
    if (threadIdx.x == 0){
        unsigned gen = *((volatile unsigned*)&g_gen);
        __threadfence();
        unsigned prev = atomicAdd(&g_arrive, 1u);
        if (prev == NB - 1){
            g_arrive = 0;
            __threadfence();
            atomicAdd(&g_gen, 1u);
        } else {
            while (*((volatile unsigned*)&g_gen) == gen) __nanosleep(64);
        }
        __threadfence();
    }
    __syncthreads();
}

// ---------------- 8-row GEMV segment ----------------
__device__ __forceinline__ void seg8(float acc[8], const float* __restrict__ W,
        int ldw, const float* __restrict__ xsp, int cnt, int lane){
    #pragma unroll 2
    for (int k = 0; k < cnt; k += 4){
        float x0 = xsp[(k+0)*32 + lane];
        float x1 = xsp[(k+1)*32 + lane];
        float x2 = xsp[(k+2)*32 + lane];
        float x3 = xsp[(k+3)*32 + lane];
        const float* wp = W + k;
        #pragma unroll
        for (int i = 0; i < 8; i++){
            float4 w = __ldg((const float4*)(wp + (size_t)i*ldw));
            acc[i] += x0*w.x + x1*w.y + x2*w.z + x3*w.w;
        }
    }
}

// ---------------- output projection (coalesced via dhB/ctxB) ----------------
__device__ __forceinline__ void proj_warps(int nwarp, int lw, int lane, int step,
        const float* __restrict__ pw, const float* __restrict__ pb, float* __restrict__ out){
    for (int o = lw; o < 2560; o += nwarp){
        int mrow = o >> 5, b = o & 31;
        float s = 0.f;
        const float4* w4 = (const float4*)(pw + (size_t)mrow*1536);
        const float4* h4 = (const float4*)(g_dhB + b*1024);
        #pragma unroll
        for (int it = 0; it < 8; it++){
            int j4 = it*32 + lane;
            float4 w = __ldg(&w4[j4]);
            float4 h = h4[j4];
            s += w.x*h.x + w.y*h.y + w.z*h.z + w.w*h.w;
        }
        const float4* c4 = (const float4*)(g_ctxB + b*512);
        #pragma unroll
        for (int it = 0; it < 4; it++){
            int j4 = it*32 + lane;
            float4 w = __ldg(&w4[256 + j4]);
            float4 c = c4[j4];
            s += w.x*c.x + w.y*c.y + w.z*c.z + w.w*c.w;
        }
        #pragma unroll
        for (int off = 16; off; off >>= 1) s += __shfl_down_sync(0xffffffffu, s, off);
        if (lane == 0) out[((size_t)b*512 + step)*80 + mrow] = s + __ldg(pb + mrow);
    }
}

// ---------------- persistent decoder ----------------
__global__ void __launch_bounds__(NT, 1) k_persist(
    const float* __restrict__ enc,
    const float* __restrict__ Qw,  const float* __restrict__ Ww,
    const float* __restrict__ Lw,  const float* __restrict__ convw,
    const float* __restrict__ awih, const float* __restrict__ awhh,
    const float* __restrict__ abih, const float* __restrict__ abhh,
    const float* __restrict__ dwih, const float* __restrict__ dwhh,
    const float* __restrict__ dbih, const float* __restrict__ dbhh,
    const float* __restrict__ pw,   const float* __restrict__ pb,
    float* __restrict__ out)
{
    extern __shared__ float sh[];
    const int tid  = threadIdx.x;
    const int bx   = blockIdx.x;
    const int gtid = bx*NT + tid;
    const int lane = tid & 31;
    const int wid  = tid >> 5;

    // zero recurrent state
    for (int i = gtid; i < 32768; i += GT){ g_ahT[i]=0.f; g_acT[i]=0.f; g_dhT[i]=0.f; g_dcT[i]=0.f; }
    for (int i = gtid; i < 32768; i += GT){ g_ahB[i]=0.f; g_dhB[i]=0.f; }
    for (int i = gtid; i < 16384; i += GT){ g_ctxT[i]=0.f; g_ctxB[i]=0.f; g_aw[i]=0.f; g_aws[i]=0.f; }

    // conv blocks: stage transposed conv weights in smem ONCE (persists all steps)
    if (bx >= 128){
        for (int i = tid; i < 992; i += NT){
            int k = i >> 5, f = i & 31;
            sh[i]       = __ldg(convw + f*62 + k);        // cwT[k][f]  (channel aw)
            sh[992 + i] = __ldg(convw + f*62 + 31 + k);   // cw2T[k][f] (channel aws)
        }
        __syncthreads();
    }
    gridbar();

    for (int step = 0; step < 512; step++){
        // ---- P1: attn GEMM (blocks 0..127) | proj(step-1) + conv paf (128..147) ----
        if (bx < 128){
            const int KS = 448;
            int kslice = bx >> 5;
            int k0 = kslice*KS;
            for (int idx = tid; idx < KS*32; idx += NT){
                int kk = idx >> 5, b = idx & 31, gk = k0 + kk;
                float v;
                if (gk < 256)      v = g_pre2T[((size_t)step*256 + gk)*32 + b];
                else if (gk < 768) v = g_ctxT[(gk-256)*32 + b];
                else               v = g_ahT[(gk-768)*32 + b];
                sh[idx] = v;
            }
            __syncthreads();
            int n0 = ((bx & 31)*16 + wid)*8;
            float acc[8];
            #pragma unroll
            for (int i = 0; i < 8; i++) acc[i] = 0.f;
            int lo = k0, hi = k0 + KS;
            int c1 = min(hi, 768) - lo;
            if (c1 > 0) seg8(acc, awih + (size_t)n0*768 + lo, 768, sh, c1, lane);
            int s2 = max(lo, 768);
            if (hi > s2) seg8(acc, awhh + (size_t)n0*1024 + (s2-768), 1024,
                              sh + (s2-k0)*32, hi - s2, lane);
            #pragma unroll
            for (int i = 0; i < 8; i++)
                g_part[((size_t)kslice*4096 + n0 + i)*32 + lane] = acc[i];
        } else {
            if (step > 0){
                int lw = (bx - 128)*16 + wid;   // 0..319
                proj_warps(320, lw, lane, step-1, pw, pb, out);
            }
            // conv: paf[b][f][t] from prev aw/aws
            for (int b = bx - 128; b < 32; b += 20){
                for (int i = tid; i < 542; i += NT){
                    int gi = i - 15;
                    bool ok = (gi >= 0 && gi < 512);
                    sh[2048+i] = ok ? g_aw [b*512 + gi] : 0.f;
                    sh[2688+i] = ok ? g_aws[b*512 + gi] : 0.f;
                }
                __syncthreads();
                float acc[32];
                #pragma unroll
                for (int f = 0; f < 32; f++) acc[f] = 0.f;
                const float4* cwT4  = (const float4*)sh;
                const float4* cw2T4 = (const float4*)(sh + 992);
                #pragma unroll 1
                for (int k = 0; k < 31; k++){
                    float a  = sh[2048 + tid + k];
                    float as = sh[2688 + tid + k];
                    #pragma unroll
                    for (int f4 = 0; f4 < 8; f4++){
                        float4 c1 = cwT4[k*8 + f4];
                        float4 c2 = cw2T4[k*8 + f4];
                        acc[f4*4+0] += a*c1.x + as*c2.x;
                        acc[f4*4+1] += a*c1.y + as*c2.y;
                        acc[f4*4+2] += a*c1.z + as*c2.z;
                        acc[f4*4+3] += a*c1.w + as*c2.w;
                    }
                }
                #pragma unroll
                for (int f = 0; f < 32; f++)
                    g_paf[(size_t)b*16384 + f*512 + tid] = acc[f];
                __syncthreads();
            }
        }
        gridbar();

        // ---- P2: attn cell + batch-major transpose (blocks 0..63) ----
        if (bx < 64){
            int j0 = bx*16, jj = tid >> 5, j = j0 + jj, b = lane;
            float gi = abih[j]      + abhh[j];
            float gf = abih[1024+j] + abhh[1024+j];
            float gg = abih[2048+j] + abhh[2048+j];
            float go = abih[3072+j] + abhh[3072+j];
            #pragma unroll
            for (int s = 0; s < 4; s++){
                const float* p = g_part + (size_t)s*4096*32;
                gi += p[(size_t)j*32+b]; gf += p[(size_t)(1024+j)*32+b];
                gg += p[(size_t)(2048+j)*32+b]; go += p[(size_t)(3072+j)*32+b];
            }
            float c  = g_acT[j*32+b];
            float c2 = sig_(gf)*c + sig_(gi)*tanh_(gg);
            float h  = sig_(go)*tanh_(c2);
            g_acT[j*32+b] = c2;
            g_ahT[j*32+b] = h;
            sh[jj*33 + b] = h;
            __syncthreads();
            int b2 = tid >> 4, j2 = tid & 15;
            g_ahB[b2*1024 + j0 + j2] = sh[j2*33 + b2];
        }
        gridbar();

        // ---- P3: q = ah @ Q^T (blocks 0..127, coalesced via ahB) ----
        {
            int gw = gtid >> 5;
            if (gw < 2048){
                #pragma unroll
                for (int u = 0; u < 2; u++){
                    int oo = gw*2 + u; int d = oo >> 5, b = oo & 31;
                    float s = 0.f;
                    const float4* q4 = (const float4*)(Qw + (size_t)d*1024);
                    const float4* h4 = (const float4*)(g_ahB + b*1024);
                    #pragma unroll
                    for (int it = 0; it < 8; it++){
                        int j4 = it*32 + lane;
                        float4 w = __ldg(&q4[j4]);
                        float4 h = h4[j4];
                        s += w.x*h.x + w.y*h.y + w.z*h.z + w.w*h.w;
                    }
                    #pragma unroll
                    for (int off = 16; off; off >>= 1) s += __shfl_down_sync(0xffffffffu, s, off);
                    if (lane == 0) g_qB[b*128 + d] = s;
                }
            }
        }
        gridbar();

        // ---- P4: energies (blocks 0..127; Lw staged in smem, interleaved d-split) ----
        if (bx < 128){
            int b = bx >> 2, t0 = (bx & 3)*128;
            for (int i = tid; i < 4096; i += NT){
                int d = i >> 5, f = i & 31;
                sh[d*36 + f] = __ldg(Lw + i);
            }
            if (tid < 128){
                sh[4608 + tid] = g_qB[b*128 + tid];
                sh[4736 + tid] = __ldg(Ww + tid);
            }
            __syncthreads();
            int t = t0 + (tid >> 2), sub = tid & 3;
            float pf[32];
            #pragma unroll
            for (int f = 0; f < 32; f++) pf[f] = g_paf[(size_t)b*16384 + f*512 + t];
            const float* pe = g_pe + ((size_t)b*512 + t)*128;
            float e = 0.f;
            #pragma unroll 1
            for (int dd = 0; dd < 32; dd++){
                int d = dd*4 + sub;
                float l = sh[4608 + d] + __ldg(pe + d);
                const float4* lw4 = (const float4*)(sh + d*36);
                #pragma unroll
                for (int i = 0; i < 8; i++){
                    float4 w = lw4[i];
                    l += pf[i*4]*w.x + pf[i*4+1]*w.y + pf[i*4+2]*w.z + pf[i*4+3]*w.w;
                }
                e += sh[4736 + d]*tanh_(l);
            }
            e += __shfl_xor_sync(0xffffffffu, e, 1);
            e += __shfl_xor_sync(0xffffffffu, e, 2);
            if (sub == 0) g_energy[b*512 + t] = e;
        }
        gridbar();

        // ---- P5: softmax (+aw/aws/align) + ctx partials (blocks 0..127) ----
        if (bx < 128){
            int b = bx & 31, kq = bx >> 5, t0 = kq*128;
            float v = g_energy[b*512 + tid];
            sh[512 + tid] = v; __syncthreads();
            for (int s = 256; s; s >>= 1){ if (tid < s) sh[512+tid] = fmaxf(sh[512+tid], sh[512+tid+s]); __syncthreads(); }
            float m = sh[512]; __syncthreads();
            float p = __expf(v - m);
            sh[512 + tid] = p; __syncthreads();
            for (int s = 256; s; s >>= 1){ if (tid < s) sh[512+tid] += sh[512+tid+s]; __syncthreads(); }
            float inv = __fdividef(1.f, sh[512]);
            float a = p*inv;
            sh[tid] = a;
            if (kq == 0){
                g_aw[b*512 + tid]   = a;
                g_aws[b*512 + tid] += a;
                out[MEL_TOT + ((size_t)b*512 + step)*512 + tid] = a;
            }
            __syncthreads();
            float acc = 0.f;
            const float* ep = enc + (size_t)b*262144 + (size_t)t0*512 + tid;
            #pragma unroll 4
            for (int t = 0; t < 128; t++) acc += sh[t0 + t]*ep[(size_t)t*512];
            g_ctxP[kq*16384 + tid*32 + b] = acc;
        }
        gridbar();

        // ---- P6: dec GEMM (blocks 0..127, inline ctx reduce) | ctx finalize (128..147) ----
        if (bx < 128){
            const int KS = 640;
            int kslice = bx >> 5;
            int k0 = kslice*KS;
            for (int idx = tid; idx < KS*32; idx += NT){
                int kk = idx >> 5, b = idx & 31, gk = k0 + kk;
                float v;
                if (gk < 1024)      v = g_ahT[gk*32 + b];
                else if (gk < 1536){
                    int o = (gk-1024)*32 + b;
                    v = ((g_ctxP[o] + g_ctxP[16384+o]) + g_ctxP[32768+o]) + g_ctxP[49152+o];
                } else               v = g_dhT[(gk-1536)*32 + b];
                sh[idx] = v;
            }
            __syncthreads();
            int n0 = ((bx & 31)*16 + wid)*8;
            float acc[8];
            #pragma unroll
            for (int i = 0; i < 8; i++) acc[i] = 0.f;
            int lo = k0, hi = k0 + KS;
            int c1 = min(hi, 1536) - lo;
            if (c1 > 0) seg8(acc, dwih + (size_t)n0*1536 + lo, 1536, sh, c1, lane);
            int s2 = max(lo, 1536);
            if (hi > s2) seg8(acc, dwhh + (size_t)n0*1024 + (s2-1536), 1024,
                              sh + (s2-k0)*32, hi - s2, lane);
            #pragma unroll
            for (int i = 0; i < 8; i++)
                g_part[((size_t)kslice*4096 + n0 + i)*32 + lane] = acc[i];
        } else {
            for (int idx = (bx-128)*NT + tid; idx < 16384; idx += 20*NT){
                float v = ((g_ctxP[idx] + g_ctxP[16384+idx]) + g_ctxP[32768+idx]) + g_ctxP[49152+idx];
                g_ctxT[idx] = v;
                int e = idx >> 5, b = idx & 31;
                g_ctxB[b*512 + e] = v;
            }
        }
        gridbar();

        // ---- P7: dec cell + batch-major transpose (blocks 0..63) ----
        if (bx < 64){
            int j0 = bx*16, jj = tid >> 5, j = j0 + jj, b = lane;
            float gi = dbih[j]      + dbhh[j];
            float gf = dbih[1024+j] + dbhh[1024+j];
            float gg = dbih[2048+j] + dbhh[2048+j];
            float go = dbih[3072+j] + dbhh[3072+j];
            #pragma unroll
            for (int s = 0; s < 4; s++){
                const float* p = g_part + (size_t)s*4096*32;
                gi += p[(size_t)j*32+b]; gf += p[(size_t)(1024+j)*32+b];
                gg += p[(size_t)(2048+j)*32+b]; go += p[(size_t)(3072+j)*32+b];
            }
            float c  = g_dcT[j*32+b];
            float c2 = sig_(gf)*c + sig_(gi)*tanh_(gg);
            float h  = sig_(go)*tanh_(c2);
            g_dcT[j*32+b] = c2;
            g_dhT[j*32+b] = h;
            sh[jj*33 + b] = h;
            __syncthreads();
            int b2 = tid >> 4, j2 = tid & 15;
            g_dhB[b2*1024 + j0 + j2] = sh[j2*33 + b2];
        }
        gridbar();
    }

    // final projection for step 511 (all blocks)
    proj_warps(NB*16, gtid >> 5, lane, 511, pw, pb, out);
}

// ---------------- launch ----------------
extern "C" void kernel_launch(void* const* d_in, const int* in_sizes, int n_in,
                              void* d_out, int out_size){
    const float* enc   = (const float*)d_in[0];
    const float* tgt   = (const float*)d_in[1];
    const float* w1    = (const float*)d_in[2];
    const float* b1    = (const float*)d_in[3];
    const float* w2    = (const float*)d_in[4];
    const float* b2    = (const float*)d_in[5];
    const float* Mw    = (const float*)d_in[6];
    const float* Qw    = (const float*)d_in[7];
    const float* Ww    = (const float*)d_in[8];
    const float* Lw    = (const float*)d_in[9];
    const float* convw = (const float*)d_in[10];
    const float* awih  = (const float*)d_in[11];
    const float* awhh  = (const float*)d_in[12];
    const float* abih  = (const float*)d_in[13];
    const float* abhh  = (const float*)d_in[14];
    const float* dwih  = (const float*)d_in[15];
    const float* dwhh  = (const float*)d_in[16];
    const float* dbih  = (const float*)d_in[17];
    const float* dbhh  = (const float*)d_in[18];
    const float* pw    = (const float*)d_in[19];
    const float* pb    = (const float*)d_in[20];
    float* out = (float*)d_out;

    k_tgtT<<<(32*512*80 + 255)/256, 256>>>(tgt);
    k_pre1<<<16384, 256>>>(w1, b1);
    k_pre2<<<16384, 256>>>(w2, b2);
    k_Mt<<<256, 256>>>(Mw);
    k_pe<<<16384, 128>>>(enc);

    cudaFuncSetAttribute(k_persist, cudaFuncAttributeMaxDynamicSharedMemorySize, 81920);
    k_persist<<<NB, NT, 81920>>>(enc, Qw, Ww, Lw, convw,
                                 awih, awhh, abih, abhh,
                                 dwih, dwhh, dbih, dbhh, pw, pb, out);
}